// round 13
// baseline (speedup 1.0000x reference)
#include <cuda_runtime.h>

#define BB 64
#define WW 4096
#define HH 128
#define II 128
#define ROWS_TOTAL (BB * WW)        /* 262144 */
#define CHUNK 896
#define NBLK ((ROWS_TOTAL + CHUNK - 1) / CHUNK)   /* 293 blocks */
#define NW 16

// Scratch (allocation-free). g_arrive is monotonic across graph replays.
// g_part entry (stride 132): [0]=batchid, [1]=ssum, [2..129]=acc
__device__ float    g_part[NBLK * 2 * 132];
__device__ unsigned g_arrive;

__device__ __forceinline__ float sigf(float x) { return 1.f / (1.f + __expf(-x)); }
__device__ __forceinline__ float dot4(float4 a, float4 b) {
    return a.x * b.x + a.y * b.y + a.z * b.z + a.w * b.w;
}
__device__ __forceinline__ float4 ldcs4(const float* p) {
    return __ldcs(reinterpret_cast<const float4*>(p));
}
__device__ __forceinline__ float red1(float a) {
    #pragma unroll
    for (int k = 16; k; k >>= 1) a += __shfl_xor_sync(0xffffffffu, a, k);
    return a;
}
__device__ __forceinline__ void red4(float& a, float& b, float& c, float& d) {
    #pragma unroll
    for (int k = 16; k; k >>= 1) {
        a += __shfl_xor_sync(0xffffffffu, a, k);
        b += __shfl_xor_sync(0xffffffffu, b, k);
        c += __shfl_xor_sync(0xffffffffu, c, k);
        d += __shfl_xor_sync(0xffffffffu, d, k);
    }
}
// reduce within 8-lane group (lanes g*8 .. g*8+7)
__device__ __forceinline__ float gred(float a) {
    a += __shfl_xor_sync(0xffffffffu, a, 4);
    a += __shfl_xor_sync(0xffffffffu, a, 2);
    a += __shfl_xor_sync(0xffffffffu, a, 1);
    return a;
}

__global__ void __launch_bounds__(512, 2) k_fused(
    const float* __restrict__ input, const float* __restrict__ h0,
    const float* __restrict__ c0, const float* __restrict__ enc,
    const float* __restrict__ attW, const float* __restrict__ attb,
    const float* __restrict__ inpW, const float* __restrict__ inpb,
    const float* __restrict__ Wih0, const float* __restrict__ Whh0,
    const float* __restrict__ bih0, const float* __restrict__ bhh0,
    const float* __restrict__ Wih1, const float* __restrict__ Whh1,
    const float* __restrict__ bih1, const float* __restrict__ bhh1,
    float* __restrict__ out)
{
    const int tid = threadIdx.x, warp = tid >> 5, lane = tid & 31;
    const int g = lane >> 3, u = lane & 7;

    __shared__ __align__(16) float sm_acc[NW][4][HH];   // 32 KB
    __shared__ __align__(16) float sm_s[NW];
    __shared__ __align__(16) float red_[4];
    __shared__ float sh_bias;

    // ======================= Phase A: attention stream =======================
    // Global rows r = b*WW + w. weight(w) = exp(logit(w)); logit(0)=0,
    // logit(w) = dot(enc row w-1, wa) + bias. Inputs ~N(0,.05^2): |logit|<<1,
    // so exp without max-subtract is exact-safe in fp32.
    //
    // Lane (g,u): 4 rows per batch (one per group g). Lane's column slice is
    // interleaved: columns {j*32 + u*4 .. +3}, j=0..3  -> every LDG.128 is a
    // contiguous 128B per 8-lane group.
    {
        const int blk = blockIdx.x;
        const int r0 = blk * CHUNK;
        const int r1 = min(r0 + CHUNK, ROWS_TOTAL);
        const int bat0 = r0 / WW;
        const int bound = (bat0 + 1) * WW;

        // wa slice for this lane (16 floats, interleaved layout)
        const float4 wv0 = *reinterpret_cast<const float4*>(attW + 0 * 32 + u * 4);
        const float4 wv1 = *reinterpret_cast<const float4*>(attW + 1 * 32 + u * 4);
        const float4 wv2 = *reinterpret_cast<const float4*>(attW + 2 * 32 + u * 4);
        const float4 wv3 = *reinterpret_cast<const float4*>(attW + 3 * 32 + u * 4);

        #pragma unroll 1
        for (int seg = 0; seg < 2; ++seg) {
            const int s0 = (seg == 0) ? r0 : min(bound, r1);
            const int s1 = (seg == 0) ? min(r1, bound) : r1;
            const int b  = bat0 + seg;
            const bool valid = (s0 < s1) && (b < BB);
            const int nrows = valid ? (s1 - s0) : 0;

            // bias_b = sum_h h0[1,b,h]*c0[1,b,h]*wa_st[h] + att_b
            if (valid && tid < HH) {
                float v = h0[(BB + b) * HH + tid] * c0[(BB + b) * HH + tid] * attW[HH + tid];
                v = red1(v);
                if (lane == 0) red_[warp] = v;
            }
            __syncthreads();
            if (tid == 0) sh_bias = valid ? (red_[0] + red_[1] + red_[2] + red_[3] + attb[0]) : 0.f;
            __syncthreads();
            const float bias = sh_bias;

            // warp row range (contiguous, multiple of 4 except clipped tail)
            int len = (nrows + 15) >> 4;
            len = (len + 3) & ~3;
            const int ws = s0 + warp * len;
            const int we = min(ws + len, s1);

            float4 ac0 = {0,0,0,0}, ac1 = {0,0,0,0}, ac2 = {0,0,0,0}, ac3 = {0,0,0,0};
            float ssum = 0.f;

            // carry = logit of the first row of this warp's range
            float carry = 0.f;
            if (ws < we && (ws - b * WW) > 0) {
                const float* rp = enc + (size_t)(ws - 1) * HH;
                float d = dot4(ldcs4(rp + 0 * 32 + u * 4), wv0)
                        + dot4(ldcs4(rp + 1 * 32 + u * 4), wv1)
                        + dot4(ldcs4(rp + 2 * 32 + u * 4), wv2)
                        + dot4(ldcs4(rp + 3 * 32 + u * 4), wv3);
                carry = gred(d) + bias;   // all groups identical -> warp-uniform
            }

            const int span = (we > ws) ? (we - ws) : 0;
            const int full_end = ws + (span & ~3);

            for (int p = ws; p < full_end; p += 4) {
                const float* rp = enc + (size_t)(p + g) * HH;
                const float4 a0 = ldcs4(rp + 0 * 32 + u * 4);
                const float4 a1 = ldcs4(rp + 1 * 32 + u * 4);
                const float4 a2 = ldcs4(rp + 2 * 32 + u * 4);
                const float4 a3 = ldcs4(rp + 3 * 32 + u * 4);
                float d = (dot4(a0, wv0) + dot4(a1, wv1))
                        + (dot4(a2, wv2) + dot4(a3, wv3));
                d = gred(d);                                   // dot of row p+g
                const float lag = __shfl_up_sync(0xffffffffu, d, 8);
                const float logit = (g == 0) ? carry : (lag + bias);
                carry = __shfl_sync(0xffffffffu, d, 24) + bias; // next batch g0
                const float e = __expf(logit);                  // weight row p+g
                ssum += e;
                ac0.x += e * a0.x; ac0.y += e * a0.y; ac0.z += e * a0.z; ac0.w += e * a0.w;
                ac1.x += e * a1.x; ac1.y += e * a1.y; ac1.z += e * a1.z; ac1.w += e * a1.w;
                ac2.x += e * a2.x; ac2.y += e * a2.y; ac2.z += e * a2.z; ac2.w += e * a2.w;
                ac3.x += e * a3.x; ac3.y += e * a3.y; ac3.z += e * a3.z; ac3.w += e * a3.w;
            }
            // tail rows (<=3): all groups load the same row; only group 0 counts
            for (int p = full_end; p < we; ++p) {
                const float* rp = enc + (size_t)p * HH;
                const float4 a0 = ldcs4(rp + 0 * 32 + u * 4);
                const float4 a1 = ldcs4(rp + 1 * 32 + u * 4);
                const float4 a2 = ldcs4(rp + 2 * 32 + u * 4);
                const float4 a3 = ldcs4(rp + 3 * 32 + u * 4);
                float d = (dot4(a0, wv0) + dot4(a1, wv1))
                        + (dot4(a2, wv2) + dot4(a3, wv3));
                d = gred(d);                       // warp-uniform
                const float e = (g == 0) ? __expf(carry) : 0.f;
                carry = d + bias;
                ssum += e;
                ac0.x += e * a0.x; ac0.y += e * a0.y; ac0.z += e * a0.z; ac0.w += e * a0.w;
                ac1.x += e * a1.x; ac1.y += e * a1.y; ac1.z += e * a1.z; ac1.w += e * a1.w;
                ac2.x += e * a2.x; ac2.y += e * a2.y; ac2.z += e * a2.z; ac2.w += e * a2.w;
                ac3.x += e * a3.x; ac3.y += e * a3.y; ac3.z += e * a3.z; ac3.w += e * a3.w;
            }

            // ---- merge: groups x warps via smem ----
            *reinterpret_cast<float4*>(&sm_acc[warp][g][0 * 32 + u * 4]) = ac0;
            *reinterpret_cast<float4*>(&sm_acc[warp][g][1 * 32 + u * 4]) = ac1;
            *reinterpret_cast<float4*>(&sm_acc[warp][g][2 * 32 + u * 4]) = ac2;
            *reinterpret_cast<float4*>(&sm_acc[warp][g][3 * 32 + u * 4]) = ac3;
            const float st = red1(ssum) * 0.125f;   // each row counted by 8 lanes
            if (lane == 0) sm_s[warp] = st;
            __syncthreads();

            float* outp = g_part + (size_t)(blk * 2 + seg) * 132;
            if (tid < HH) {
                float a = 0.f;
                #pragma unroll
                for (int j = 0; j < NW; ++j) {
                    a += (sm_acc[j][0][tid] + sm_acc[j][1][tid])
                       + (sm_acc[j][2][tid] + sm_acc[j][3][tid]);
                }
                outp[2 + tid] = a;
            }
            if (tid == 0) {
                float stt = 0.f;
                #pragma unroll
                for (int j = 0; j < NW; ++j) stt += sm_s[j];
                outp[0] = valid ? (float)b : -1.f;
                outp[1] = stt;
            }
            __syncthreads();   // smem reuse for next segment
        }
    }

    // ============ grid barrier (monotonic; non-post blocks just arrive) ======
    if (blockIdx.x >= BB) {
        if (tid == 0) {
            __threadfence();
            atomicAdd(&g_arrive, 1u);
        }
        return;
    }
    if (tid == 0) {
        __threadfence();
        const unsigned t1 = atomicAdd(&g_arrive, 1u) + 1u;
        const unsigned target = ((t1 + NBLK - 1u) / NBLK) * NBLK;
        while (atomicAdd(&g_arrive, 0u) < target) __nanosleep(64);
        __threadfence();
    }
    __syncthreads();

    // ======================= Phase B: xin + 2x LSTM ==========================
    const int b = blockIdx.x;
    __shared__ __align__(16) float s_cat[HH + II];
    __shared__ __align__(16) float s_x[HH];
    __shared__ __align__(16) float s_h[HH];
    __shared__ __align__(16) float s_g[4 * HH];
    __shared__ __align__(16) float s_bs0[4 * HH];
    __shared__ __align__(16) float s_bs1[4 * HH];

    if (tid < HH) {
        const int i_lo = (b * WW) / CHUNK;
        const int i_hi = ((b + 1) * WW - 1) / CHUNK;
        const float fb = (float)b;
        float den = 0.f, a = 0.f;
        for (int i = i_lo; i <= i_hi; ++i) {
            #pragma unroll
            for (int seg = 0; seg < 2; ++seg) {
                const float* e = g_part + (size_t)(i * 2 + seg) * 132;
                if (__ldcg(e) == fb) {
                    den += __ldcg(e + 1);
                    a   += __ldcg(e + 2 + tid);
                }
            }
        }
        s_cat[tid]      = a / den;
        s_cat[HH + tid] = input[b * II + tid];
        s_h[tid]        = h0[b * HH + tid];
    }
    for (int i = tid; i < 4 * HH; i += 512) {
        s_bs0[i] = bih0[i] + bhh0[i];
        s_bs1[i] = bih1[i] + bhh1[i];
    }
    __syncthreads();

    // ---- xin = [x, input] @ inp_W.T + b : 8 rows/warp ----
    {
        const float4 cA = *reinterpret_cast<const float4*>(s_cat + lane * 4);
        const float4 cB = *reinterpret_cast<const float4*>(s_cat + HH + lane * 4);
        #pragma unroll
        for (int i = 0; i < 8; i += 4) {
            const int j = warp * 8 + i;
            float d[4];
            #pragma unroll
            for (int q = 0; q < 4; ++q) {
                const float4 wA = *reinterpret_cast<const float4*>(inpW + (size_t)(j + q) * (HH + II) + lane * 4);
                const float4 wB = *reinterpret_cast<const float4*>(inpW + (size_t)(j + q) * (HH + II) + HH + lane * 4);
                d[q] = dot4(wA, cA) + dot4(wB, cB);
            }
            red4(d[0], d[1], d[2], d[3]);
            if (lane == 0) {
                #pragma unroll
                for (int q = 0; q < 4; ++q) s_x[j + q] = d[q] + inpb[j + q];
            }
        }
    }
    __syncthreads();

    // Output layout: output[B*H] | h1 | h2 | c1 | c2
    const int OUT_O  = 0;
    const int OUT_H0 = BB * HH;
    const int OUT_H1 = OUT_H0 + BB * HH;
    const int OUT_C0 = OUT_H1 + BB * HH;
    const int OUT_C1 = OUT_C0 + BB * HH;
    const int idx = b * HH + (tid & 127);

    // ---- layer 0 : warp computes j = warp*32 .. +31 ----
    {
        const float4 xv = *reinterpret_cast<const float4*>(s_x + lane * 4);
        const float4 hv = *reinterpret_cast<const float4*>(s_h + lane * 4);
        #pragma unroll
        for (int i = 0; i < 32; i += 4) {
            const int j = warp * 32 + i;
            float d[4];
            #pragma unroll
            for (int q = 0; q < 4; ++q) {
                const float4 wi = *reinterpret_cast<const float4*>(Wih0 + (size_t)(j + q) * HH + lane * 4);
                const float4 wh = *reinterpret_cast<const float4*>(Whh0 + (size_t)(j + q) * HH + lane * 4);
                d[q] = dot4(wi, xv) + dot4(wh, hv);
            }
            red4(d[0], d[1], d[2], d[3]);
            if (lane == 0) {
                #pragma unroll
                for (int q = 0; q < 4; ++q) s_g[j + q] = d[q] + s_bs0[j + q];
            }
        }
    }
    __syncthreads();
    if (tid < HH) {
        const float c1 = sigf(s_g[HH + tid]) * c0[idx] + sigf(s_g[tid]) * tanhf(s_g[2 * HH + tid]);
        const float h1 = sigf(s_g[3 * HH + tid]) * tanhf(c1);
        out[OUT_H0 + idx] = h1;
        out[OUT_C0 + idx] = c1;
        s_x[tid] = h1;                       // layer-1 input
        s_h[tid] = h0[BB * HH + idx];        // layer-1 hprev
    }
    __syncthreads();

    // ---- layer 1 ----
    {
        const float4 xv = *reinterpret_cast<const float4*>(s_x + lane * 4);
        const float4 hv = *reinterpret_cast<const float4*>(s_h + lane * 4);
        #pragma unroll
        for (int i = 0; i < 32; i += 4) {
            const int j = warp * 32 + i;
            float d[4];
            #pragma unroll
            for (int q = 0; q < 4; ++q) {
                const float4 wi = *reinterpret_cast<const float4*>(Wih1 + (size_t)(j + q) * HH + lane * 4);
                const float4 wh = *reinterpret_cast<const float4*>(Whh1 + (size_t)(j + q) * HH + lane * 4);
                d[q] = dot4(wi, xv) + dot4(wh, hv);
            }
            red4(d[0], d[1], d[2], d[3]);
            if (lane == 0) {
                #pragma unroll
                for (int q = 0; q < 4; ++q) s_g[j + q] = d[q] + s_bs1[j + q];
            }
        }
    }
    __syncthreads();
    if (tid < HH) {
        const float c2 = sigf(s_g[HH + tid]) * c0[BB * HH + idx] + sigf(s_g[tid]) * tanhf(s_g[2 * HH + tid]);
        const float h2 = sigf(s_g[3 * HH + tid]) * tanhf(c2);
        out[OUT_H1 + idx] = h2;
        out[OUT_C1 + idx] = c2;
        out[OUT_O  + idx] = h2;
    }
}

// ---------------------------------------------------------------------------
extern "C" void kernel_launch(void* const* d_in, const int* in_sizes, int n_in,
                              void* d_out, int out_size)
{
    (void)in_sizes; (void)n_in; (void)out_size;
    k_fused<<<NBLK, 512>>>(
        (const float*)d_in[0],  (const float*)d_in[1],  (const float*)d_in[2],
        (const float*)d_in[3],  (const float*)d_in[4],  (const float*)d_in[5],
        (const float*)d_in[6],  (const float*)d_in[7],  (const float*)d_in[8],
        (const float*)d_in[9],  (const float*)d_in[10], (const float*)d_in[11],
        (const float*)d_in[12], (const float*)d_in[13], (const float*)d_in[14],
        (const float*)d_in[15], (float*)d_out);
}

// round 14
// speedup vs baseline: 1.0263x; 1.0263x over previous
#include <cuda_runtime.h>
#include <cstdint>

#define BB 64
#define WW 4096
#define HH 128
#define II 128
#define NBLK 128               /* 2 blocks per batch, all resident (occ 1)  */
#define HALF 2048              /* rows per block                            */
#define TROWS 64               /* rows per tile (32 KB)                     */
#define NTILES (HALF / TROWS)  /* 32                                       */
#define DEPTH 4                /* smem ring depth                           */
#define TILE_F (TROWS * HH)    /* 8192 floats                               */
#define DYN_BYTES (DEPTH * TILE_F * 4)   /* 131072 B dynamic smem           */
#define NW 16

// Scratch (allocation-free). g_arrive is monotonic across graph replays.
// g_part entry (stride 132): [0]=ssum, [1..128]=acc columns
__device__ float    g_part[NBLK * 132];
__device__ unsigned g_arrive;

__device__ __forceinline__ float sigf(float x) { return 1.f / (1.f + __expf(-x)); }
__device__ __forceinline__ float dot4(float4 a, float4 b) {
    return a.x * b.x + a.y * b.y + a.z * b.z + a.w * b.w;
}
__device__ __forceinline__ float red1(float a) {
    #pragma unroll
    for (int k = 16; k; k >>= 1) a += __shfl_xor_sync(0xffffffffu, a, k);
    return a;
}
__device__ __forceinline__ void red4(float& a, float& b, float& c, float& d) {
    #pragma unroll
    for (int k = 16; k; k >>= 1) {
        a += __shfl_xor_sync(0xffffffffu, a, k);
        b += __shfl_xor_sync(0xffffffffu, b, k);
        c += __shfl_xor_sync(0xffffffffu, c, k);
        d += __shfl_xor_sync(0xffffffffu, d, k);
    }
}

__device__ __forceinline__ void issue_tile(const float* __restrict__ enc,
                                           int row0, int T, float* dyn, int tid)
{
    const float4* gsrc = reinterpret_cast<const float4*>(enc + (size_t)(row0 + T * TROWS) * HH);
    uint32_t sb = (uint32_t)__cvta_generic_to_shared(dyn + (size_t)(T & (DEPTH - 1)) * TILE_F);
    #pragma unroll
    for (int k = 0; k < 4; ++k) {
        const int idx = tid + k * 512;
        asm volatile("cp.async.cg.shared.global [%0], [%1], 16;"
                     :: "r"(sb + idx * 16), "l"(gsrc + idx) : "memory");
    }
    asm volatile("cp.async.commit_group;" ::: "memory");
}

__global__ void __launch_bounds__(512, 1) k_fused(
    const float* __restrict__ input, const float* __restrict__ h0,
    const float* __restrict__ c0, const float* __restrict__ enc,
    const float* __restrict__ attW, const float* __restrict__ attb,
    const float* __restrict__ inpW, const float* __restrict__ inpb,
    const float* __restrict__ Wih0, const float* __restrict__ Whh0,
    const float* __restrict__ bih0, const float* __restrict__ bhh0,
    const float* __restrict__ Wih1, const float* __restrict__ Whh1,
    const float* __restrict__ bih1, const float* __restrict__ bhh1,
    float* __restrict__ out)
{
    extern __shared__ __align__(16) float dyn[];   // DEPTH x 64 x 128 tile ring
    const int tid = threadIdx.x, warp = tid >> 5, lane = tid & 31;

    __shared__ __align__(16) float sm_acc[NW][HH];
    __shared__ __align__(16) float sm_s[NW];
    __shared__ __align__(16) float red_[4];
    __shared__ float sh_bias;

    // ======================= Phase A: attention stream =======================
    // weight(row r)=exp(dot(enc row r-1, wa)+bias); weight(row 0)=1.
    // Inputs ~N(0,.05^2): |logit|<<1 -> exp without max-subtract is safe.
    {
        const int blk = blockIdx.x;
        const int b = blk >> 1, s = blk & 1;
        const int row0 = b * WW + s * HALF;

        const float4 wav = *reinterpret_cast<const float4*>(attW + lane * 4);

        // prefetch first tiles ASAP
        issue_tile(enc, row0, 0, dyn, tid);
        issue_tile(enc, row0, 1, dyn, tid);
        issue_tile(enc, row0, 2, dyn, tid);

        // bias_b = sum_h h0[1,b,h]*c0[1,b,h]*wa_st[h] + att_b
        if (tid < HH) {
            float v = h0[(BB + b) * HH + tid] * c0[(BB + b) * HH + tid] * attW[HH + tid];
            v = red1(v);
            if (lane == 0) red_[warp] = v;
        }
        // raw lag dot for s==1 (row row0-1), warp-redundant but cheap
        float rawlag = 0.f;
        if (s == 1) {
            const float4 rm = *reinterpret_cast<const float4*>(enc + (size_t)(row0 - 1) * HH + lane * 4);
            rawlag = red1(dot4(rm, wav));
        }
        __syncthreads();
        if (tid == 0) sh_bias = red_[0] + red_[1] + red_[2] + red_[3] + attb[0];
        __syncthreads();
        const float bias = sh_bias;
        const float lag0 = (s == 1) ? (rawlag + bias) : 0.f;   // logit of first row

        float4 acc = {0.f, 0.f, 0.f, 0.f};
        float ssum = 0.f;

        #pragma unroll 1
        for (int t = 0; t < NTILES; ++t) {
            asm volatile("cp.async.wait_group 2;" ::: "memory");
            __syncthreads();                      // tile t visible to all

            const float* buf = dyn + (size_t)(t & (DEPTH - 1)) * TILE_F;

            float4 rm1;
            if (warp == 0) {
                if (t == 0) rm1 = make_float4(0.f, 0.f, 0.f, 0.f);
                else rm1 = *reinterpret_cast<const float4*>(
                         dyn + (size_t)((t - 1) & (DEPTH - 1)) * TILE_F + 63 * HH + lane * 4);
            } else {
                rm1 = *reinterpret_cast<const float4*>(buf + (warp * 4 - 1) * HH + lane * 4);
            }
            const float4 r0 = *reinterpret_cast<const float4*>(buf + (warp * 4 + 0) * HH + lane * 4);
            const float4 r1 = *reinterpret_cast<const float4*>(buf + (warp * 4 + 1) * HH + lane * 4);
            const float4 r2 = *reinterpret_cast<const float4*>(buf + (warp * 4 + 2) * HH + lane * 4);
            const float4 r3 = *reinterpret_cast<const float4*>(buf + (warp * 4 + 3) * HH + lane * 4);

            float d0 = dot4(rm1, wav);
            float d1 = dot4(r0, wav);
            float d2 = dot4(r1, wav);
            float d3 = dot4(r2, wav);
            red4(d0, d1, d2, d3);

            const float l0 = (warp == 0 && t == 0) ? lag0 : (d0 + bias);
            const float e0 = __expf(l0);
            const float e1 = __expf(d1 + bias);
            const float e2 = __expf(d2 + bias);
            const float e3 = __expf(d3 + bias);

            ssum += (e0 + e1) + (e2 + e3);
            acc.x += e0 * r0.x + e1 * r1.x + e2 * r2.x + e3 * r3.x;
            acc.y += e0 * r0.y + e1 * r1.y + e2 * r2.y + e3 * r3.y;
            acc.z += e0 * r0.z + e1 * r1.z + e2 * r2.z + e3 * r3.z;
            acc.w += e0 * r0.w + e1 * r1.w + e2 * r2.w + e3 * r3.w;

            __syncthreads();                      // done reading buffers t, t-1
            if (t + DEPTH - 1 < NTILES) issue_tile(enc, row0, t + DEPTH - 1, dyn, tid);
        }

        // ---- block merge ----
        *reinterpret_cast<float4*>(&sm_acc[warp][lane * 4]) = acc;
        if (lane == 0) sm_s[warp] = ssum;         // warp-uniform value
        __syncthreads();

        float* outp = g_part + (size_t)blk * 132;
        if (tid < HH) {
            float a = 0.f;
            #pragma unroll
            for (int j = 0; j < NW; ++j) a += sm_acc[j][tid];
            outp[1 + tid] = a;
        }
        if (tid == 0) {
            float st = 0.f;
            #pragma unroll
            for (int j = 0; j < NW; ++j) st += sm_s[j];
            outp[0] = st;
        }
    }

    // ============ grid barrier (monotonic; non-post blocks just arrive) ======
    if (blockIdx.x >= BB) {
        if (tid == 0) {
            __threadfence();
            atomicAdd(&g_arrive, 1u);
        }
        return;
    }
    if (tid == 0) {
        __threadfence();
        const unsigned t1 = atomicAdd(&g_arrive, 1u) + 1u;
        const unsigned target = ((t1 + NBLK - 1u) / NBLK) * NBLK;
        while (atomicAdd(&g_arrive, 0u) < target) __nanosleep(64);
        __threadfence();
    }
    __syncthreads();

    // ======================= Phase B: xin + 2x LSTM ==========================
    const int b = blockIdx.x;
    __shared__ __align__(16) float s_cat[HH + II];
    __shared__ __align__(16) float s_x[HH];
    __shared__ __align__(16) float s_h[HH];
    __shared__ __align__(16) float s_g[4 * HH];
    __shared__ __align__(16) float s_bs0[4 * HH];
    __shared__ __align__(16) float s_bs1[4 * HH];

    if (tid < HH) {
        const float* p0 = g_part + (size_t)(b * 2 + 0) * 132;
        const float* p1 = g_part + (size_t)(b * 2 + 1) * 132;
        const float den = __ldcg(p0) + __ldcg(p1);
        const float a   = __ldcg(p0 + 1 + tid) + __ldcg(p1 + 1 + tid);
        s_cat[tid]      = a / den;
        s_cat[HH + tid] = input[b * II + tid];
        s_h[tid]        = h0[b * HH + tid];
    }
    for (int i = tid; i < 4 * HH; i += 512) {
        s_bs0[i] = bih0[i] + bhh0[i];
        s_bs1[i] = bih1[i] + bhh1[i];
    }
    __syncthreads();

    // ---- xin = [x, input] @ inp_W.T + b : 8 rows/warp ----
    {
        const float4 cA = *reinterpret_cast<const float4*>(s_cat + lane * 4);
        const float4 cB = *reinterpret_cast<const float4*>(s_cat + HH + lane * 4);
        #pragma unroll
        for (int i = 0; i < 8; i += 4) {
            const int j = warp * 8 + i;
            float d[4];
            #pragma unroll
            for (int q = 0; q < 4; ++q) {
                const float4 wA = *reinterpret_cast<const float4*>(inpW + (size_t)(j + q) * (HH + II) + lane * 4);
                const float4 wB = *reinterpret_cast<const float4*>(inpW + (size_t)(j + q) * (HH + II) + HH + lane * 4);
                d[q] = dot4(wA, cA) + dot4(wB, cB);
            }
            red4(d[0], d[1], d[2], d[3]);
            if (lane == 0) {
                #pragma unroll
                for (int q = 0; q < 4; ++q) s_x[j + q] = d[q] + inpb[j + q];
            }
        }
    }
    __syncthreads();

    // Output layout: output[B*H] | h1 | h2 | c1 | c2
    const int OUT_O  = 0;
    const int OUT_H0 = BB * HH;
    const int OUT_H1 = OUT_H0 + BB * HH;
    const int OUT_C0 = OUT_H1 + BB * HH;
    const int OUT_C1 = OUT_C0 + BB * HH;
    const int idx = b * HH + (tid & 127);

    // ---- layer 0 : warp computes j = warp*32 .. +31 ----
    {
        const float4 xv = *reinterpret_cast<const float4*>(s_x + lane * 4);
        const float4 hv = *reinterpret_cast<const float4*>(s_h + lane * 4);
        #pragma unroll
        for (int i = 0; i < 32; i += 4) {
            const int j = warp * 32 + i;
            float d[4];
            #pragma unroll
            for (int q = 0; q < 4; ++q) {
                const float4 wi = *reinterpret_cast<const float4*>(Wih0 + (size_t)(j + q) * HH + lane * 4);
                const float4 wh = *reinterpret_cast<const float4*>(Whh0 + (size_t)(j + q) * HH + lane * 4);
                d[q] = dot4(wi, xv) + dot4(wh, hv);
            }
            red4(d[0], d[1], d[2], d[3]);
            if (lane == 0) {
                #pragma unroll
                for (int q = 0; q < 4; ++q) s_g[j + q] = d[q] + s_bs0[j + q];
            }
        }
    }
    __syncthreads();
    if (tid < HH) {
        const float c1 = sigf(s_g[HH + tid]) * c0[idx] + sigf(s_g[tid]) * tanhf(s_g[2 * HH + tid]);
        const float h1 = sigf(s_g[3 * HH + tid]) * tanhf(c1);
        out[OUT_H0 + idx] = h1;
        out[OUT_C0 + idx] = c1;
        s_x[tid] = h1;                       // layer-1 input
        s_h[tid] = h0[BB * HH + idx];        // layer-1 hprev
    }
    __syncthreads();

    // ---- layer 1 ----
    {
        const float4 xv = *reinterpret_cast<const float4*>(s_x + lane * 4);
        const float4 hv = *reinterpret_cast<const float4*>(s_h + lane * 4);
        #pragma unroll
        for (int i = 0; i < 32; i += 4) {
            const int j = warp * 32 + i;
            float d[4];
            #pragma unroll
            for (int q = 0; q < 4; ++q) {
                const float4 wi = *reinterpret_cast<const float4*>(Wih1 + (size_t)(j + q) * HH + lane * 4);
                const float4 wh = *reinterpret_cast<const float4*>(Whh1 + (size_t)(j + q) * HH + lane * 4);
                d[q] = dot4(wi, xv) + dot4(wh, hv);
            }
            red4(d[0], d[1], d[2], d[3]);
            if (lane == 0) {
                #pragma unroll
                for (int q = 0; q < 4; ++q) s_g[j + q] = d[q] + s_bs1[j + q];
            }
        }
    }
    __syncthreads();
    if (tid < HH) {
        const float c2 = sigf(s_g[HH + tid]) * c0[BB * HH + idx] + sigf(s_g[tid]) * tanhf(s_g[2 * HH + tid]);
        const float h2 = sigf(s_g[3 * HH + tid]) * tanhf(c2);
        out[OUT_H1 + idx] = h2;
        out[OUT_C1 + idx] = c2;
        out[OUT_O  + idx] = h2;
    }
}

// ---------------------------------------------------------------------------
extern "C" void kernel_launch(void* const* d_in, const int* in_sizes, int n_in,
                              void* d_out, int out_size)
{
    (void)in_sizes; (void)n_in; (void)out_size;
    cudaFuncSetAttribute(k_fused, cudaFuncAttributeMaxDynamicSharedMemorySize, DYN_BYTES);
    k_fused<<<NBLK, 512, DYN_BYTES>>>(
        (const float*)d_in[0],  (const float*)d_in[1],  (const float*)d_in[2],
        (const float*)d_in[3],  (const float*)d_in[4],  (const float*)d_in[5],
        (const float*)d_in[6],  (const float*)d_in[7],  (const float*)d_in[8],
        (const float*)d_in[9],  (const float*)d_in[10], (const float*)d_in[11],
        (const float*)d_in[12], (const float*)d_in[13], (const float*)d_in[14],
        (const float*)d_in[15], (float*)d_out);
}

// round 15
// speedup vs baseline: 1.0620x; 1.0348x over previous
#include <cuda_runtime.h>
#include <cstdint>

#define BB 64
#define WW 4096
#define HH 128
#define II 128
#define NBLK 128               /* 2 blocks per batch, all resident (occ 1)  */
#define HALF 2048              /* rows per block                            */
#define TROWS 64               /* rows per tile (32 KB)                     */
#define NTILES (HALF / TROWS)  /* 32                                       */
#define DEPTH 4                /* smem ring depth                           */
#define TILE_F (TROWS * HH)    /* 8192 floats                               */
#define TILE_BYTES (TILE_F * 4)          /* 32768 B                         */
#define DYN_BYTES (DEPTH * TILE_BYTES)   /* 131072 B dynamic smem           */
#define NW 16

// Scratch (allocation-free). g_arrive is monotonic across graph replays.
// g_part entry (stride 132): [0]=ssum, [1..128]=acc columns
__device__ float    g_part[NBLK * 132];
__device__ unsigned g_arrive;

__device__ __forceinline__ float sigf(float x) { return 1.f / (1.f + __expf(-x)); }
__device__ __forceinline__ float dot4(float4 a, float4 b) {
    return a.x * b.x + a.y * b.y + a.z * b.z + a.w * b.w;
}
__device__ __forceinline__ float red1(float a) {
    #pragma unroll
    for (int k = 16; k; k >>= 1) a += __shfl_xor_sync(0xffffffffu, a, k);
    return a;
}
__device__ __forceinline__ void red4(float& a, float& b, float& c, float& d) {
    #pragma unroll
    for (int k = 16; k; k >>= 1) {
        a += __shfl_xor_sync(0xffffffffu, a, k);
        b += __shfl_xor_sync(0xffffffffu, b, k);
        c += __shfl_xor_sync(0xffffffffu, c, k);
        d += __shfl_xor_sync(0xffffffffu, d, k);
    }
}

__device__ __forceinline__ uint32_t s2u(const void* p) {
    return (uint32_t)__cvta_generic_to_shared(p);
}
__device__ __forceinline__ void mbar_init(uint32_t mbar, uint32_t cnt) {
    asm volatile("mbarrier.init.shared.b64 [%0], %1;" :: "r"(mbar), "r"(cnt) : "memory");
}
__device__ __forceinline__ void mbar_expect_tx(uint32_t mbar, uint32_t bytes) {
    asm volatile("mbarrier.arrive.expect_tx.shared.b64 _, [%0], %1;" :: "r"(mbar), "r"(bytes) : "memory");
}
__device__ __forceinline__ void mbar_wait(uint32_t mbar, uint32_t parity) {
    uint32_t done;
    asm volatile(
        "{\n\t.reg .pred p;\n\t"
        "mbarrier.try_wait.parity.acquire.cta.shared::cta.b64 p, [%1], %2;\n\t"
        "selp.b32 %0, 1, 0, p;\n\t}"
        : "=r"(done) : "r"(mbar), "r"(parity) : "memory");
    if (!done) {
        asm volatile(
            "{\n\t.reg .pred P1;\n\t"
            "WL_%=:\n\t"
            "mbarrier.try_wait.parity.acquire.cta.shared::cta.b64 P1, [%0], %1, 0x989680;\n\t"
            "@P1 bra.uni WD_%=;\n\t"
            "bra.uni WL_%=;\n\t"
            "WD_%=:\n\t}"
            :: "r"(mbar), "r"(parity) : "memory");
    }
}
// 1D TMA bulk copy: global -> shared::cta, completion via mbarrier tx bytes
__device__ __forceinline__ void tma_bulk_1d(uint32_t dst_smem, const void* src, uint32_t bytes, uint32_t mbar) {
    asm volatile(
        "cp.async.bulk.shared::cta.global.mbarrier::complete_tx::bytes [%0], [%1], %2, [%3];"
        :: "r"(dst_smem), "l"(src), "r"(bytes), "r"(mbar) : "memory");
}

__global__ void __launch_bounds__(512, 1) k_fused(
    const float* __restrict__ input, const float* __restrict__ h0,
    const float* __restrict__ c0, const float* __restrict__ enc,
    const float* __restrict__ attW, const float* __restrict__ attb,
    const float* __restrict__ inpW, const float* __restrict__ inpb,
    const float* __restrict__ Wih0, const float* __restrict__ Whh0,
    const float* __restrict__ bih0, const float* __restrict__ bhh0,
    const float* __restrict__ Wih1, const float* __restrict__ Whh1,
    const float* __restrict__ bih1, const float* __restrict__ bhh1,
    float* __restrict__ out)
{
    extern __shared__ __align__(16) float dyn[];   // DEPTH x 64 x 128 tile ring
    const int tid = threadIdx.x, warp = tid >> 5, lane = tid & 31;

    __shared__ __align__(16) float sm_acc[NW][HH];
    __shared__ __align__(16) float sm_s[NW];
    __shared__ __align__(16) float red_[4];
    __shared__ float sh_bias;
    __shared__ __align__(8) unsigned long long s_mbar[DEPTH];

    // ======================= Phase A: attention stream =======================
    // weight(row r)=exp(dot(enc row r-1, wa)+bias); weight(row 0)=1.
    // Inputs ~N(0,.05^2): |logit|<<1 -> exp without max-subtract is safe.
    {
        const int blk = blockIdx.x;
        const int b = blk >> 1, s = blk & 1;
        const int row0 = b * WW + s * HALF;

        const float4 wav = *reinterpret_cast<const float4*>(attW + lane * 4);

        // init mbarriers, then prefetch first tiles via TMA bulk
        if (tid == 0) {
            #pragma unroll
            for (int d = 0; d < DEPTH; ++d) mbar_init(s2u(&s_mbar[d]), 1);
        }
        __syncthreads();
        if (tid == 0) {
            #pragma unroll
            for (int T = 0; T < DEPTH - 1; ++T) {
                const uint32_t mb = s2u(&s_mbar[T]);
                mbar_expect_tx(mb, TILE_BYTES);
                tma_bulk_1d(s2u(dyn + (size_t)T * TILE_F),
                            enc + (size_t)(row0 + T * TROWS) * HH, TILE_BYTES, mb);
            }
        }

        // bias_b = sum_h h0[1,b,h]*c0[1,b,h]*wa_st[h] + att_b
        if (tid < HH) {
            float v = h0[(BB + b) * HH + tid] * c0[(BB + b) * HH + tid] * attW[HH + tid];
            v = red1(v);
            if (lane == 0) red_[warp] = v;
        }
        // raw lag dot for s==1 (row row0-1), warp-redundant but cheap
        float rawlag = 0.f;
        if (s == 1) {
            const float4 rm = *reinterpret_cast<const float4*>(enc + (size_t)(row0 - 1) * HH + lane * 4);
            rawlag = red1(dot4(rm, wav));
        }
        __syncthreads();
        if (tid == 0) sh_bias = red_[0] + red_[1] + red_[2] + red_[3] + attb[0];
        __syncthreads();
        const float bias = sh_bias;
        const float lag0 = (s == 1) ? (rawlag + bias) : 0.f;   // logit of first row

        float4 acc = {0.f, 0.f, 0.f, 0.f};
        float ssum = 0.f;

        #pragma unroll 1
        for (int t = 0; t < NTILES; ++t) {
            mbar_wait(s2u(&s_mbar[t & (DEPTH - 1)]), (t >> 2) & 1);

            const float* buf = dyn + (size_t)(t & (DEPTH - 1)) * TILE_F;

            float4 rm1;
            if (warp == 0) {
                if (t == 0) rm1 = make_float4(0.f, 0.f, 0.f, 0.f);
                else rm1 = *reinterpret_cast<const float4*>(
                         dyn + (size_t)((t - 1) & (DEPTH - 1)) * TILE_F + 63 * HH + lane * 4);
            } else {
                rm1 = *reinterpret_cast<const float4*>(buf + (warp * 4 - 1) * HH + lane * 4);
            }
            const float4 r0 = *reinterpret_cast<const float4*>(buf + (warp * 4 + 0) * HH + lane * 4);
            const float4 r1 = *reinterpret_cast<const float4*>(buf + (warp * 4 + 1) * HH + lane * 4);
            const float4 r2 = *reinterpret_cast<const float4*>(buf + (warp * 4 + 2) * HH + lane * 4);
            const float4 r3 = *reinterpret_cast<const float4*>(buf + (warp * 4 + 3) * HH + lane * 4);

            float d0 = dot4(rm1, wav);
            float d1 = dot4(r0, wav);
            float d2 = dot4(r1, wav);
            float d3 = dot4(r2, wav);
            red4(d0, d1, d2, d3);

            const float l0 = (warp == 0 && t == 0) ? lag0 : (d0 + bias);
            const float e0 = __expf(l0);
            const float e1 = __expf(d1 + bias);
            const float e2 = __expf(d2 + bias);
            const float e3 = __expf(d3 + bias);

            ssum += (e0 + e1) + (e2 + e3);
            acc.x += e0 * r0.x + e1 * r1.x + e2 * r2.x + e3 * r3.x;
            acc.y += e0 * r0.y + e1 * r1.y + e2 * r2.y + e3 * r3.y;
            acc.z += e0 * r0.z + e1 * r1.z + e2 * r2.z + e3 * r3.z;
            acc.w += e0 * r0.w + e1 * r1.w + e2 * r2.w + e3 * r3.w;

            __syncthreads();          // everyone done reading slots t, t-1
            if (tid == 0 && t + DEPTH - 1 < NTILES) {
                const int T = t + DEPTH - 1;
                const uint32_t mb = s2u(&s_mbar[T & (DEPTH - 1)]);
                mbar_expect_tx(mb, TILE_BYTES);
                tma_bulk_1d(s2u(dyn + (size_t)(T & (DEPTH - 1)) * TILE_F),
                            enc + (size_t)(row0 + T * TROWS) * HH, TILE_BYTES, mb);
            }
        }

        // ---- block merge ----
        *reinterpret_cast<float4*>(&sm_acc[warp][lane * 4]) = acc;
        if (lane == 0) sm_s[warp] = ssum;         // warp-uniform value
        __syncthreads();

        float* outp = g_part + (size_t)blk * 132;
        if (tid < HH) {
            float a = 0.f;
            #pragma unroll
            for (int j = 0; j < NW; ++j) a += sm_acc[j][tid];
            outp[1 + tid] = a;
        }
        if (tid == 0) {
            float st = 0.f;
            #pragma unroll
            for (int j = 0; j < NW; ++j) st += sm_s[j];
            outp[0] = st;
        }
    }

    // ============ grid barrier (monotonic; non-post blocks just arrive) ======
    if (blockIdx.x >= BB) {
        if (tid == 0) {
            __threadfence();
            atomicAdd(&g_arrive, 1u);
        }
        return;
    }
    if (tid == 0) {
        __threadfence();
        const unsigned t1 = atomicAdd(&g_arrive, 1u) + 1u;
        const unsigned target = ((t1 + NBLK - 1u) / NBLK) * NBLK;
        while (atomicAdd(&g_arrive, 0u) < target) __nanosleep(64);
        __threadfence();
    }
    __syncthreads();

    // ======================= Phase B: xin + 2x LSTM ==========================
    const int b = blockIdx.x;
    __shared__ __align__(16) float s_cat[HH + II];
    __shared__ __align__(16) float s_x[HH];
    __shared__ __align__(16) float s_h[HH];
    __shared__ __align__(16) float s_g[4 * HH];
    __shared__ __align__(16) float s_bs0[4 * HH];
    __shared__ __align__(16) float s_bs1[4 * HH];

    if (tid < HH) {
        const float* p0 = g_part + (size_t)(b * 2 + 0) * 132;
        const float* p1 = g_part + (size_t)(b * 2 + 1) * 132;
        const float den = __ldcg(p0) + __ldcg(p1);
        const float a   = __ldcg(p0 + 1 + tid) + __ldcg(p1 + 1 + tid);
        s_cat[tid]      = a / den;
        s_cat[HH + tid] = input[b * II + tid];
        s_h[tid]        = h0[b * HH + tid];
    }
    for (int i = tid; i < 4 * HH; i += 512) {
        s_bs0[i] = bih0[i] + bhh0[i];
        s_bs1[i] = bih1[i] + bhh1[i];
    }
    __syncthreads();

    // ---- xin = [x, input] @ inp_W.T + b : 8 rows/warp ----
    {
        const float4 cA = *reinterpret_cast<const float4*>(s_cat + lane * 4);
        const float4 cB = *reinterpret_cast<const float4*>(s_cat + HH + lane * 4);
        #pragma unroll
        for (int i = 0; i < 8; i += 4) {
            const int j = warp * 8 + i;
            float d[4];
            #pragma unroll
            for (int q = 0; q < 4; ++q) {
                const float4 wA = *reinterpret_cast<const float4*>(inpW + (size_t)(j + q) * (HH + II) + lane * 4);
                const float4 wB = *reinterpret_cast<const float4*>(inpW + (size_t)(j + q) * (HH + II) + HH + lane * 4);
                d[q] = dot4(wA, cA) + dot4(wB, cB);
            }
            red4(d[0], d[1], d[2], d[3]);
            if (lane == 0) {
                #pragma unroll
                for (int q = 0; q < 4; ++q) s_x[j + q] = d[q] + inpb[j + q];
            }
        }
    }
    __syncthreads();

    // Output layout: output[B*H] | h1 | h2 | c1 | c2
    const int OUT_O  = 0;
    const int OUT_H0 = BB * HH;
    const int OUT_H1 = OUT_H0 + BB * HH;
    const int OUT_C0 = OUT_H1 + BB * HH;
    const int OUT_C1 = OUT_C0 + BB * HH;
    const int idx = b * HH + (tid & 127);

    // ---- layer 0 : warp computes j = warp*32 .. +31 ----
    {
        const float4 xv = *reinterpret_cast<const float4*>(s_x + lane * 4);
        const float4 hv = *reinterpret_cast<const float4*>(s_h + lane * 4);
        #pragma unroll
        for (int i = 0; i < 32; i += 4) {
            const int j = warp * 32 + i;
            float d[4];
            #pragma unroll
            for (int q = 0; q < 4; ++q) {
                const float4 wi = *reinterpret_cast<const float4*>(Wih0 + (size_t)(j + q) * HH + lane * 4);
                const float4 wh = *reinterpret_cast<const float4*>(Whh0 + (size_t)(j + q) * HH + lane * 4);
                d[q] = dot4(wi, xv) + dot4(wh, hv);
            }
            red4(d[0], d[1], d[2], d[3]);
            if (lane == 0) {
                #pragma unroll
                for (int q = 0; q < 4; ++q) s_g[j + q] = d[q] + s_bs0[j + q];
            }
        }
    }
    __syncthreads();
    if (tid < HH) {
        const float c1 = sigf(s_g[HH + tid]) * c0[idx] + sigf(s_g[tid]) * tanhf(s_g[2 * HH + tid]);
        const float h1 = sigf(s_g[3 * HH + tid]) * tanhf(c1);
        out[OUT_H0 + idx] = h1;
        out[OUT_C0 + idx] = c1;
        s_x[tid] = h1;                       // layer-1 input
        s_h[tid] = h0[BB * HH + idx];        // layer-1 hprev
    }
    __syncthreads();

    // ---- layer 1 ----
    {
        const float4 xv = *reinterpret_cast<const float4*>(s_x + lane * 4);
        const float4 hv = *reinterpret_cast<const float4*>(s_h + lane * 4);
        #pragma unroll
        for (int i = 0; i < 32; i += 4) {
            const int j = warp * 32 + i;
            float d[4];
            #pragma unroll
            for (int q = 0; q < 4; ++q) {
                const float4 wi = *reinterpret_cast<const float4*>(Wih1 + (size_t)(j + q) * HH + lane * 4);
                const float4 wh = *reinterpret_cast<const float4*>(Whh1 + (size_t)(j + q) * HH + lane * 4);
                d[q] = dot4(wi, xv) + dot4(wh, hv);
            }
            red4(d[0], d[1], d[2], d[3]);
            if (lane == 0) {
                #pragma unroll
                for (int q = 0; q < 4; ++q) s_g[j + q] = d[q] + s_bs1[j + q];
            }
        }
    }
    __syncthreads();
    if (tid < HH) {
        const float c2 = sigf(s_g[HH + tid]) * c0[BB * HH + idx] + sigf(s_g[tid]) * tanhf(s_g[2 * HH + tid]);
        const float h2 = sigf(s_g[3 * HH + tid]) * tanhf(c2);
        out[OUT_H1 + idx] = h2;
        out[OUT_C1 + idx] = c2;
        out[OUT_O  + idx] = h2;
    }
}

// ---------------------------------------------------------------------------
extern "C" void kernel_launch(void* const* d_in, const int* in_sizes, int n_in,
                              void* d_out, int out_size)
{
    (void)in_sizes; (void)n_in; (void)out_size;
    cudaFuncSetAttribute(k_fused, cudaFuncAttributeMaxDynamicSharedMemorySize, DYN_BYTES);
    k_fused<<<NBLK, 512, DYN_BYTES>>>(
        (const float*)d_in[0],  (const float*)d_in[1],  (const float*)d_in[2],
        (const float*)d_in[3],  (const float*)d_in[4],  (const float*)d_in[5],
        (const float*)d_in[6],  (const float*)d_in[7],  (const float*)d_in[8],
        (const float*)d_in[9],  (const float*)d_in[10], (const float*)d_in[11],
        (const float*)d_in[12], (const float*)d_in[13], (const float*)d_in[14],
        (const float*)d_in[15], (float*)d_out);
}